// round 1
// baseline (speedup 1.0000x reference)
#include <cuda_runtime.h>
#include <stdint.h>

// Problem constants (fixed by the dataset)
#define KG_MAX 200000
#define B_MAX  20000
#define E_MAX  640000
#define IN_DIM 256
#define OUT_DIM 128

// ---------------- device scratch (no dynamic allocation allowed) ----------------
__device__ int   g_is64;
__device__ __align__(16) float g_vL[IN_DIM];   // W^T @ w_atten[:128]
__device__ __align__(16) float g_vR[IN_DIM];   // W^T @ w_atten[128:]
__device__ float g_cLR;                        // b.(waL+waR)
__device__ int   g_cnt[B_MAX];
__device__ int   g_cur[B_MAX];
__device__ int   g_off[B_MAX + 1];
__device__ int   g_csr[E_MAX];                 // stores edge ids
__device__ __align__(16) float g_Wt[IN_DIM * OUT_DIM];   // W transposed: [k][n]
__device__ __align__(16) float g_Y[(size_t)B_MAX * IN_DIM]; // agg/rowsum, [B,256]

__device__ __forceinline__ int ld_idx(const void* p, long long i, int is64) {
    return is64 ? (int)((const long long*)p)[i] : ((const int*)p)[i];
}

// ---------------- k_prep: dtype detect, vL/vR/cLR, W transpose, zero counters ---
__global__ void k_prep(const void* __restrict__ bids,
                       const float* __restrict__ W,
                       const float* __restrict__ bias,
                       const float* __restrict__ wa,
                       int B) {
    int t = threadIdx.x;  // 256 threads
    __shared__ int s_nz;
    if (t == 0) s_nz = 0;
    __syncthreads();
    // If data is int64 (values < 2^31, nonneg), every odd 32-bit word is 0.
    // batch_ids has 20000 elements -> >= 512 32-bit words readable either way.
    const unsigned int* u = (const unsigned int*)bids;
    if (u[2 * t + 1] != 0u) atomicOr(&s_nz, 1);
    __syncthreads();
    if (t == 0) g_is64 = s_nz ? 0 : 1;

    // vL[k] = sum_n W[n,k]*wa[n] ; vR[k] = sum_n W[n,k]*wa[128+n]
    float vl = 0.f, vr = 0.f;
#pragma unroll 4
    for (int n = 0; n < OUT_DIM; n++) {
        float w = W[n * IN_DIM + t];
        vl = fmaf(w, wa[n], vl);
        vr = fmaf(w, wa[OUT_DIM + n], vr);
    }
    g_vL[t] = vl;
    g_vR[t] = vr;

    // cLR = sum_n b[n]*(wa[n]+wa[n+128])
    __shared__ float sr[256];
    sr[t] = (t < OUT_DIM) ? bias[t] * (wa[t] + wa[t + OUT_DIM]) : 0.f;
    __syncthreads();
    for (int off = 128; off > 0; off >>= 1) {
        if (t < off) sr[t] += sr[t + off];
        __syncthreads();
    }
    if (t == 0) g_cLR = sr[0];

    // W transpose -> g_Wt[k*128+n] = W[n*256+k]
    for (int idx = t; idx < OUT_DIM * IN_DIM; idx += 256) {
        int k = idx >> 7, n = idx & 127;
        g_Wt[idx] = W[n * IN_DIM + k];
    }
    // zero per-row counters
    for (int i = t; i < B; i += 256) { g_cnt[i] = 0; g_cur[i] = 0; }
}

// ---------------- k_hist: per-row degree ----------------
__global__ void k_hist(const void* __restrict__ ei, int E) {
    int e = blockIdx.x * blockDim.x + threadIdx.x;
    if (e >= E) return;
    int r = ld_idx(ei, e, g_is64);
    atomicAdd(&g_cnt[r], 1);
}

// ---------------- k_scan: exclusive scan of degrees (1 block) ----------------
__global__ void k_scan(int B) {
    __shared__ int s[1024];
    int t = threadIdx.x;
    int CH = (B + 1023) >> 10;
    int lo = t * CH;
    int hi = min(lo + CH, B);
    int sum = 0;
    for (int i = lo; i < hi; i++) sum += g_cnt[i];
    s[t] = sum;
    __syncthreads();
    for (int off = 1; off < 1024; off <<= 1) {
        int v = (t >= off) ? s[t - off] : 0;
        __syncthreads();
        s[t] += v;
        __syncthreads();
    }
    int run = (t == 0) ? 0 : s[t - 1];
    for (int i = lo; i < hi; i++) { g_off[i] = run; run += g_cnt[i]; }
    if (t == 1023) g_off[B] = s[1023];
}

// ---------------- k_scatter: build CSR (stores edge ids) ----------------
__global__ void k_scatter(const void* __restrict__ ei, int E) {
    int e = blockIdx.x * blockDim.x + threadIdx.x;
    if (e >= E) return;
    int r = ld_idx(ei, e, g_is64);
    int pos = atomicAdd(&g_cur[r], 1);
    g_csr[g_off[r] + pos] = e;
}

// ---------------- k_agg: fused gather + attention + aggregate ----------------
// One block (256 thr = 8 warps) per output row. Each warp handles edges
// i = w, w+8, ... Each lane owns 8 consecutive embed columns (2x float4).
// Edge list is bitonic-sorted (by edge id) for bitwise-deterministic fp32 sums.
__global__ void __launch_bounds__(256) k_agg(const float* __restrict__ ent,
                                             const void* __restrict__ bids,
                                             const void* __restrict__ ei,
                                             int E, int B) {
    __shared__ int   s_e[512];
    __shared__ float s_red[8 * 256];
    __shared__ float s_as[8];
    __shared__ float s_sl[8];

    int r = blockIdx.x;
    if (r >= B) return;
    int t = threadIdx.x, w = t >> 5, lane = t & 31;
    int is64 = g_is64;
    int off0 = g_off[r];
    int deg  = g_off[r + 1] - off0;

    // sL = ent[batch_ids[r]] . vL  (block-wide, 1 elem/thread + warp reduce)
    long long gi = is64 ? ((const long long*)bids)[r]
                        : (long long)((const int*)bids)[r];
    float p = ent[gi * (long long)IN_DIM + t] * g_vL[t];
#pragma unroll
    for (int o = 16; o > 0; o >>= 1) p += __shfl_down_sync(0xffffffffu, p, o);
    if (lane == 0) s_sl[w] = p;

    bool staged = (deg <= 512);
    if (staged) {
        int P = 1;
        while (P < deg) P <<= 1;
        for (int i = t; i < P; i += 256)
            s_e[i] = (i < deg) ? g_csr[off0 + i] : 0x7fffffff;
        __syncthreads();
        for (int k = 2; k <= P; k <<= 1) {
            for (int j = k >> 1; j > 0; j >>= 1) {
                for (int i = t; i < P; i += 256) {
                    int ixj = i ^ j;
                    if (ixj > i) {
                        int a = s_e[i], c = s_e[ixj];
                        bool up = ((i & k) == 0);
                        if ((a > c) == up) { s_e[i] = c; s_e[ixj] = a; }
                    }
                }
                __syncthreads();
            }
        }
    } else {
        __syncthreads();
    }

    // block total of sL partials (fixed order -> deterministic)
    float sLtot = 0.f;
#pragma unroll
    for (int w2 = 0; w2 < 8; w2++) sLtot += s_sl[w2];
    float base = sLtot + g_cLR;  // score = base + x.vR

    float4 vr0 = *(const float4*)&g_vR[lane * 8];
    float4 vr1 = *(const float4*)&g_vR[lane * 8 + 4];
    float4 A0 = make_float4(0.f, 0.f, 0.f, 0.f);
    float4 A1 = make_float4(0.f, 0.f, 0.f, 0.f);
    float asum = 0.f;

    for (int i = w; i < deg; i += 8) {
        int e = staged ? s_e[i] : g_csr[off0 + i];
        long long c = is64 ? ((const long long*)ei)[(long long)E + e]
                           : (long long)((const int*)ei)[E + e];
        const float* xr = ent + c * (long long)IN_DIM + lane * 8;
        float4 x0 = *(const float4*)xr;
        float4 x1 = *(const float4*)(xr + 4);
        float d = x0.x * vr0.x + x0.y * vr0.y + x0.z * vr0.z + x0.w * vr0.w
                + x1.x * vr1.x + x1.y * vr1.y + x1.z * vr1.z + x1.w * vr1.w;
#pragma unroll
        for (int o = 16; o > 0; o >>= 1) d += __shfl_xor_sync(0xffffffffu, d, o);
        float score = base + d;
        float v = score >= 0.f ? score : 0.2f * score;  // leaky_relu(0.2)
        float att = __expf(-v);
        asum += att;
        A0.x = fmaf(att, x0.x, A0.x); A0.y = fmaf(att, x0.y, A0.y);
        A0.z = fmaf(att, x0.z, A0.z); A0.w = fmaf(att, x0.w, A0.w);
        A1.x = fmaf(att, x1.x, A1.x); A1.y = fmaf(att, x1.y, A1.y);
        A1.z = fmaf(att, x1.z, A1.z); A1.w = fmaf(att, x1.w, A1.w);
    }

    float* rp = &s_red[w * 256 + lane * 8];
    rp[0] = A0.x; rp[1] = A0.y; rp[2] = A0.z; rp[3] = A0.w;
    rp[4] = A1.x; rp[5] = A1.y; rp[6] = A1.z; rp[7] = A1.w;
    if (lane == 0) s_as[w] = asum;
    __syncthreads();

    float atot = 0.f;
#pragma unroll
    for (int w2 = 0; w2 < 8; w2++) atot += s_as[w2];
    float ys = s_red[t];
#pragma unroll
    for (int w2 = 1; w2 < 8; w2++) ys += s_red[w2 * 256 + t];
    g_Y[(size_t)r * IN_DIM + t] = ys / atot;
}

// ---------------- k_gemm: out = prelu(Y @ Wt + b) ----------------
// C[M=20000, N=128], K=256. Tile 64(M) x 128(N) per 256-thread block,
// 8x4 microtile per thread. Warp w owns M-rows [w*8, w*8+8) (a broadcast).
__global__ void __launch_bounds__(256) k_gemm(const float* __restrict__ bias,
                                              const float* __restrict__ prelu,
                                              float* __restrict__ out, int M) {
    const int BM = 64, BN = 128, BK = 16;
    __shared__ __align__(16) float Ys[BK][BM];
    __shared__ __align__(16) float Ws[BK][BN];

    int tid = threadIdx.x;
    int m0 = blockIdx.x * BM;
    int tmg = tid >> 5;   // 0..7 : M group (8 rows)
    int tng = tid & 31;   // 0..31: N group (4 cols)

    float acc[8][4];
#pragma unroll
    for (int i = 0; i < 8; i++)
#pragma unroll
        for (int j = 0; j < 4; j++) acc[i][j] = 0.f;

    for (int kt = 0; kt < IN_DIM; kt += BK) {
        // stage Y tile (64 rows x 16 k), transposed into Ys[k][m]
        {
            int mr = tid >> 2;
            int kc = (tid & 3) << 2;
            float4 v = make_float4(0.f, 0.f, 0.f, 0.f);
            int row = m0 + mr;
            if (row < M) v = *(const float4*)&g_Y[(size_t)row * IN_DIM + kt + kc];
            Ys[kc + 0][mr] = v.x; Ys[kc + 1][mr] = v.y;
            Ys[kc + 2][mr] = v.z; Ys[kc + 3][mr] = v.w;
        }
        // stage Wt tile (16 k x 128 n)
#pragma unroll
        for (int i = 0; i < 2; i++) {
            int idx = tid + i * 256;
            int kr = idx >> 5;
            int nc = (idx & 31) << 2;
            *(float4*)&Ws[kr][nc] = *(const float4*)&g_Wt[(kt + kr) * OUT_DIM + nc];
        }
        __syncthreads();
#pragma unroll
        for (int k = 0; k < BK; k++) {
            float4 a0 = *(const float4*)&Ys[k][tmg * 8];
            float4 a1 = *(const float4*)&Ys[k][tmg * 8 + 4];
            float4 bb = *(const float4*)&Ws[k][tng * 4];
            float a[8] = {a0.x, a0.y, a0.z, a0.w, a1.x, a1.y, a1.z, a1.w};
            float bv[4] = {bb.x, bb.y, bb.z, bb.w};
#pragma unroll
            for (int i = 0; i < 8; i++)
#pragma unroll
                for (int j = 0; j < 4; j++)
                    acc[i][j] = fmaf(a[i], bv[j], acc[i][j]);
        }
        __syncthreads();
    }

    float pw = prelu[0];
    float b0 = bias[tng * 4 + 0], b1 = bias[tng * 4 + 1];
    float b2 = bias[tng * 4 + 2], b3 = bias[tng * 4 + 3];
#pragma unroll
    for (int i = 0; i < 8; i++) {
        int row = m0 + tmg * 8 + i;
        if (row < M) {
            float4 o;
            o.x = acc[i][0] + b0; o.y = acc[i][1] + b1;
            o.z = acc[i][2] + b2; o.w = acc[i][3] + b3;
            o.x = o.x >= 0.f ? o.x : pw * o.x;
            o.y = o.y >= 0.f ? o.y : pw * o.y;
            o.z = o.z >= 0.f ? o.z : pw * o.z;
            o.w = o.w >= 0.f ? o.w : pw * o.w;
            *(float4*)&out[(size_t)row * OUT_DIM + tng * 4] = o;
        }
    }
}

// ---------------- launch ----------------
extern "C" void kernel_launch(void* const* d_in, const int* in_sizes, int n_in,
                              void* d_out, int out_size) {
    const float* ent  = (const float*)d_in[0];
    const void*  bids = d_in[1];
    const void*  ei   = d_in[2];
    const float* W    = (const float*)d_in[3];
    const float* bias = (const float*)d_in[4];
    const float* wa   = (const float*)d_in[5];
    const float* pw   = (const float*)d_in[6];

    int B = in_sizes[1];
    int E = in_sizes[2] / 2;
    if (B > B_MAX) B = B_MAX;
    if (E > E_MAX) E = E_MAX;

    k_prep<<<1, 256>>>(bids, W, bias, wa, B);
    k_hist<<<(E + 255) / 256, 256>>>(ei, E);
    k_scan<<<1, 1024>>>(B);
    k_scatter<<<(E + 255) / 256, 256>>>(ei, E);
    k_agg<<<B, 256>>>(ent, bids, ei, E, B);
    k_gemm<<<(B + 63) / 64, 256>>>(bias, pw, (float*)d_out, B);
}

// round 2
// speedup vs baseline: 1.4391x; 1.4391x over previous
#include <cuda_runtime.h>
#include <stdint.h>

#define KG_MAX 200000
#define B_MAX  20000
#define E_MAX  640000
#define IN_DIM 256
#define OUT_DIM 128

// ---------------- device scratch ----------------
__device__ int   g_is64;
__device__ __align__(16) float g_vL[IN_DIM];
__device__ __align__(16) float g_vR[IN_DIM];
__device__ float g_cLR;
__device__ float g_dR[KG_MAX];                 // ent[v] . vR
__device__ float g_sL[B_MAX];                  // ent[bid[r]] . vL + cLR
__device__ int   g_cnt[B_MAX];
__device__ int   g_cur[B_MAX];
__device__ int   g_off[B_MAX + 1];
__device__ int   g_csr[E_MAX];
__device__ __align__(16) float g_Wt[IN_DIM * OUT_DIM];       // [k][n]
__device__ __align__(16) float g_Y[(size_t)B_MAX * IN_DIM];  // [B,256]

__device__ __forceinline__ int ld_row(const void* p, int e, int is64) {
    return is64 ? (int)((const long long*)p)[e] : ((const int*)p)[e];
}
__device__ __forceinline__ int ld_col(const void* p, int E, int e, int is64) {
    return is64 ? (int)((const long long*)p)[(long long)E + e]
                : ((const int*)p)[E + e];
}

// ---------------- k_prep ----------------
__global__ void k_prep(const void* __restrict__ bids,
                       const float* __restrict__ W,
                       const float* __restrict__ bias,
                       const float* __restrict__ wa,
                       int B) {
    int t = threadIdx.x;  // 256
    __shared__ int s_nz;
    if (t == 0) s_nz = 0;
    __syncthreads();
    const unsigned int* u = (const unsigned int*)bids;
    if (u[2 * t + 1] != 0u) atomicOr(&s_nz, 1);
    __syncthreads();
    if (t == 0) g_is64 = s_nz ? 0 : 1;

    float vl = 0.f, vr = 0.f;
#pragma unroll 4
    for (int n = 0; n < OUT_DIM; n++) {
        float w = W[n * IN_DIM + t];
        vl = fmaf(w, wa[n], vl);
        vr = fmaf(w, wa[OUT_DIM + n], vr);
    }
    g_vL[t] = vl;
    g_vR[t] = vr;

    __shared__ float sr[256];
    sr[t] = (t < OUT_DIM) ? bias[t] * (wa[t] + wa[t + OUT_DIM]) : 0.f;
    __syncthreads();
    for (int off = 128; off > 0; off >>= 1) {
        if (t < off) sr[t] += sr[t + off];
        __syncthreads();
    }
    if (t == 0) g_cLR = sr[0];

    for (int idx = t; idx < OUT_DIM * IN_DIM; idx += 256) {
        int k = idx >> 7, n = idx & 127;
        g_Wt[idx] = W[n * IN_DIM + k];
    }
    for (int i = t; i < B; i += 256) { g_cnt[i] = 0; g_cur[i] = 0; }
}

// ---------------- k_fused: dR stream + sL gather + degree histogram --------
__global__ void __launch_bounds__(256) k_fused(
        const float* __restrict__ ent, const void* __restrict__ bids,
        const void* __restrict__ ei, int KG, int B, int E,
        int nbdr, int nbsl) {
    int bid = blockIdx.x;
    int t = threadIdx.x, w = t >> 5, lane = t & 31;
    if (bid < nbdr) {
        int v = bid * 8 + w;
        if (v < KG) {
            const float* x = ent + (size_t)v * IN_DIM + lane * 8;
            float4 x0 = *(const float4*)x;
            float4 x1 = *(const float4*)(x + 4);
            float4 r0 = *(const float4*)&g_vR[lane * 8];
            float4 r1 = *(const float4*)&g_vR[lane * 8 + 4];
            float d = x0.x * r0.x + x0.y * r0.y + x0.z * r0.z + x0.w * r0.w
                    + x1.x * r1.x + x1.y * r1.y + x1.z * r1.z + x1.w * r1.w;
#pragma unroll
            for (int o = 16; o > 0; o >>= 1)
                d += __shfl_xor_sync(0xffffffffu, d, o);
            if (lane == 0) g_dR[v] = d;
        }
    } else if (bid < nbdr + nbsl) {
        int r = (bid - nbdr) * 8 + w;
        if (r < B) {
            long long gi = g_is64 ? ((const long long*)bids)[r]
                                  : (long long)((const int*)bids)[r];
            const float* x = ent + gi * (long long)IN_DIM + lane * 8;
            float4 x0 = *(const float4*)x;
            float4 x1 = *(const float4*)(x + 4);
            float4 l0 = *(const float4*)&g_vL[lane * 8];
            float4 l1 = *(const float4*)&g_vL[lane * 8 + 4];
            float d = x0.x * l0.x + x0.y * l0.y + x0.z * l0.z + x0.w * l0.w
                    + x1.x * l1.x + x1.y * l1.y + x1.z * l1.z + x1.w * l1.w;
#pragma unroll
            for (int o = 16; o > 0; o >>= 1)
                d += __shfl_xor_sync(0xffffffffu, d, o);
            if (lane == 0) g_sL[r] = d + g_cLR;
        }
    } else {
        int e = (bid - nbdr - nbsl) * 256 + t;
        if (e < E) {
            int r = ld_row(ei, e, g_is64);
            atomicAdd(&g_cnt[r], 1);
        }
    }
}

// ---------------- k_scan ----------------
__global__ void k_scan(int B) {
    __shared__ int s[1024];
    int t = threadIdx.x;
    int CH = (B + 1023) >> 10;
    int lo = t * CH, hi = min(lo + CH, B);
    int sum = 0;
    for (int i = lo; i < hi; i++) sum += g_cnt[i];
    s[t] = sum;
    __syncthreads();
    for (int off = 1; off < 1024; off <<= 1) {
        int v = (t >= off) ? s[t - off] : 0;
        __syncthreads();
        s[t] += v;
        __syncthreads();
    }
    int run = (t == 0) ? 0 : s[t - 1];
    for (int i = lo; i < hi; i++) { g_off[i] = run; run += g_cnt[i]; }
    if (t == 1023) g_off[B] = s[1023];
}

// ---------------- k_scatter ----------------
__global__ void k_scatter(const void* __restrict__ ei, int E) {
    int e = blockIdx.x * blockDim.x + threadIdx.x;
    if (e >= E) return;
    int r = ld_row(ei, e, g_is64);
    int pos = atomicAdd(&g_cur[r], 1);
    g_csr[g_off[r] + pos] = e;
}

// ---------------- k_agg: warp per row ----------------
// Lane owns 8 embed columns. att = exp(-lrelu(sL[r] + dR[c])) is a scalar
// lookup per edge (no per-edge dot product). 32 edges' att computed in
// parallel, then broadcast via shfl into an independent gather/fma stream.
__global__ void __launch_bounds__(256) k_agg(const float* __restrict__ ent,
                                             const void* __restrict__ ei,
                                             int E, int B) {
    __shared__ int s_e[8][128];
    int t = threadIdx.x, w = t >> 5, lane = t & 31;
    int r = blockIdx.x * 8 + w;
    if (r >= B) return;
    int is64 = g_is64;
    int off0 = g_off[r];
    int deg = g_off[r + 1] - off0;
    float base = g_sL[r];

    const float* entl = ent + lane * 8;
    float4 A0 = make_float4(0.f, 0.f, 0.f, 0.f);
    float4 A1 = make_float4(0.f, 0.f, 0.f, 0.f);
    float asum = 0.f;

    if (deg <= 128) {
        int P = 1;
        while (P < deg) P <<= 1;
        for (int i = lane; i < P; i += 32)
            s_e[w][i] = (i < deg) ? g_csr[off0 + i] : 0x7fffffff;
        __syncwarp();
        for (int k = 2; k <= P; k <<= 1) {
            for (int j = k >> 1; j > 0; j >>= 1) {
                for (int i = lane; i < P; i += 32) {
                    int ixj = i ^ j;
                    if (ixj > i) {
                        int a = s_e[w][i], c = s_e[w][ixj];
                        bool up = ((i & k) == 0);
                        if ((a > c) == up) { s_e[w][i] = c; s_e[w][ixj] = a; }
                    }
                }
                __syncwarp();
            }
        }
        for (int b0 = 0; b0 < deg; b0 += 32) {
            int n = min(32, deg - b0);
            int c = 0;
            float att = 0.f;
            if (lane < n) {
                int e = s_e[w][b0 + lane];
                c = ld_col(ei, E, e, is64);
                float s = base + g_dR[c];
                float v = s >= 0.f ? s : 0.2f * s;
                att = __expf(-v);
            }
            for (int j = 0; j < n; j++) {
                float a = __shfl_sync(0xffffffffu, att, j);
                int cj = __shfl_sync(0xffffffffu, c, j);
                const float* x = entl + (size_t)cj * IN_DIM;
                float4 x0 = *(const float4*)x;
                float4 x1 = *(const float4*)(x + 4);
                asum += a;
                A0.x = fmaf(a, x0.x, A0.x); A0.y = fmaf(a, x0.y, A0.y);
                A0.z = fmaf(a, x0.z, A0.z); A0.w = fmaf(a, x0.w, A0.w);
                A1.x = fmaf(a, x1.x, A1.x); A1.y = fmaf(a, x1.y, A1.y);
                A1.z = fmaf(a, x1.z, A1.z); A1.w = fmaf(a, x1.w, A1.w);
            }
        }
    } else {
        // deterministic fallback: process edges in increasing edge-id order
        int last = -1;
        for (int rk = 0; rk < deg; rk++) {
            int m = 0x7fffffff;
            for (int i = lane; i < deg; i += 32) {
                int ec = g_csr[off0 + i];
                if (ec > last && ec < m) m = ec;
            }
#pragma unroll
            for (int o = 16; o > 0; o >>= 1)
                m = min(m, __shfl_xor_sync(0xffffffffu, m, o));
            int c = ld_col(ei, E, m, is64);
            float s = base + g_dR[c];
            float v = s >= 0.f ? s : 0.2f * s;
            float a = __expf(-v);
            const float* x = entl + (size_t)c * IN_DIM;
            float4 x0 = *(const float4*)x;
            float4 x1 = *(const float4*)(x + 4);
            asum += a;
            A0.x = fmaf(a, x0.x, A0.x); A0.y = fmaf(a, x0.y, A0.y);
            A0.z = fmaf(a, x0.z, A0.z); A0.w = fmaf(a, x0.w, A0.w);
            A1.x = fmaf(a, x1.x, A1.x); A1.y = fmaf(a, x1.y, A1.y);
            A1.z = fmaf(a, x1.z, A1.z); A1.w = fmaf(a, x1.w, A1.w);
            last = m;
        }
    }

    float inv = 1.0f / asum;  // asum identical across lanes (same sequence)
    float* y = &g_Y[(size_t)r * IN_DIM + lane * 8];
    float4 o0, o1;
    o0.x = A0.x * inv; o0.y = A0.y * inv; o0.z = A0.z * inv; o0.w = A0.w * inv;
    o1.x = A1.x * inv; o1.y = A1.y * inv; o1.z = A1.z * inv; o1.w = A1.w * inv;
    *(float4*)y = o0;
    *(float4*)(y + 4) = o1;
}

// ---------------- k_gemm: out = prelu(Y @ Wt + b), 128x128x16 tile, 8x8 ----
__global__ void __launch_bounds__(256) k_gemm(const float* __restrict__ bias,
                                              const float* __restrict__ prelu,
                                              float* __restrict__ out, int M) {
    const int BK = 16;
    __shared__ __align__(16) float Ys[BK][128];
    __shared__ __align__(16) float Ws[BK][128];

    int tid = threadIdx.x;
    int m0 = blockIdx.x * 128;
    int tm = tid >> 4;    // 0..15 -> 8 rows each
    int tn = tid & 15;    // 0..15 -> 8 cols each

    float acc[8][8];
#pragma unroll
    for (int i = 0; i < 8; i++)
#pragma unroll
        for (int j = 0; j < 8; j++) acc[i][j] = 0.f;

    for (int kt = 0; kt < IN_DIM; kt += BK) {
        // stage Y tile: 128 rows x 16 k, transpose into Ys[k][m]
#pragma unroll
        for (int i = 0; i < 2; i++) {
            int f = tid * 2 + i;          // 0..511 float4 slots
            int mr = f >> 2;
            int kc = (f & 3) << 2;
            float4 v = make_float4(0.f, 0.f, 0.f, 0.f);
            int row = m0 + mr;
            if (row < M) v = *(const float4*)&g_Y[(size_t)row * IN_DIM + kt + kc];
            Ys[kc + 0][mr] = v.x; Ys[kc + 1][mr] = v.y;
            Ys[kc + 2][mr] = v.z; Ys[kc + 3][mr] = v.w;
        }
        // stage Wt tile: 16 k x 128 n
#pragma unroll
        for (int i = 0; i < 2; i++) {
            int idx = tid + i * 256;
            int kr = idx >> 5;
            int nc = (idx & 31) << 2;
            *(float4*)&Ws[kr][nc] = *(const float4*)&g_Wt[(kt + kr) * OUT_DIM + nc];
        }
        __syncthreads();
#pragma unroll
        for (int k = 0; k < BK; k++) {
            float4 a0 = *(const float4*)&Ys[k][tm * 8];
            float4 a1 = *(const float4*)&Ys[k][tm * 8 + 4];
            float4 b0 = *(const float4*)&Ws[k][tn * 8];
            float4 b1 = *(const float4*)&Ws[k][tn * 8 + 4];
            float a[8] = {a0.x, a0.y, a0.z, a0.w, a1.x, a1.y, a1.z, a1.w};
            float bb[8] = {b0.x, b0.y, b0.z, b0.w, b1.x, b1.y, b1.z, b1.w};
#pragma unroll
            for (int i = 0; i < 8; i++)
#pragma unroll
                for (int j = 0; j < 8; j++)
                    acc[i][j] = fmaf(a[i], bb[j], acc[i][j]);
        }
        __syncthreads();
    }

    float pw = prelu[0];
    float bv[8];
#pragma unroll
    for (int j = 0; j < 8; j++) bv[j] = bias[tn * 8 + j];
#pragma unroll
    for (int i = 0; i < 8; i++) {
        int row = m0 + tm * 8 + i;
        if (row < M) {
            float4 o0, o1;
            float v0 = acc[i][0] + bv[0], v1 = acc[i][1] + bv[1];
            float v2 = acc[i][2] + bv[2], v3 = acc[i][3] + bv[3];
            float v4 = acc[i][4] + bv[4], v5 = acc[i][5] + bv[5];
            float v6 = acc[i][6] + bv[6], v7 = acc[i][7] + bv[7];
            o0.x = v0 >= 0.f ? v0 : pw * v0; o0.y = v1 >= 0.f ? v1 : pw * v1;
            o0.z = v2 >= 0.f ? v2 : pw * v2; o0.w = v3 >= 0.f ? v3 : pw * v3;
            o1.x = v4 >= 0.f ? v4 : pw * v4; o1.y = v5 >= 0.f ? v5 : pw * v5;
            o1.z = v6 >= 0.f ? v6 : pw * v6; o1.w = v7 >= 0.f ? v7 : pw * v7;
            *(float4*)&out[(size_t)row * OUT_DIM + tn * 8] = o0;
            *(float4*)&out[(size_t)row * OUT_DIM + tn * 8 + 4] = o1;
        }
    }
}

// ---------------- launch ----------------
extern "C" void kernel_launch(void* const* d_in, const int* in_sizes, int n_in,
                              void* d_out, int out_size) {
    const float* ent  = (const float*)d_in[0];
    const void*  bids = d_in[1];
    const void*  ei   = d_in[2];
    const float* W    = (const float*)d_in[3];
    const float* bias = (const float*)d_in[4];
    const float* wa   = (const float*)d_in[5];
    const float* pw   = (const float*)d_in[6];

    int KG = in_sizes[0] / IN_DIM;
    int B  = in_sizes[1];
    int E  = in_sizes[2] / 2;
    if (KG > KG_MAX) KG = KG_MAX;
    if (B > B_MAX) B = B_MAX;
    if (E > E_MAX) E = E_MAX;

    int nbdr = (KG + 7) / 8;
    int nbsl = (B + 7) / 8;
    int nbh  = (E + 255) / 256;

    k_prep<<<1, 256>>>(bids, W, bias, wa, B);
    k_fused<<<nbdr + nbsl + nbh, 256>>>(ent, bids, ei, KG, B, E, nbdr, nbsl);
    k_scan<<<1, 1024>>>(B);
    k_scatter<<<(E + 255) / 256, 256>>>(ei, E);
    k_agg<<<(B + 7) / 8, 256>>>(ent, ei, E, B);
    k_gemm<<<(B + 127) / 128, 256>>>(bias, pw, (float*)d_out, B);
}